// round 1
// baseline (speedup 1.0000x reference)
#include <cuda_runtime.h>
#include <cstdint>

// ---------------------------------------------------------------------------
// MultiHeadAttention: B=4, S=2048, E=1024, H=16, D=64, fp32
// out = softmax((q@Wq+bq)(k@Wk+bk)^T / 8) @ (v@Wv+bv) @ Wo + bo
// ---------------------------------------------------------------------------

#define B_    4
#define S_    2048
#define E_    1024
#define H_    16
#define D_    64
#define M_    (B_ * S_)          // 8192 rows for all projections

// Scratch (device globals -- no allocation allowed)
__device__ float g_Q[M_ * E_];
__device__ float g_K[M_ * E_];
__device__ float g_V[M_ * E_];
__device__ float g_O[M_ * E_];

// ---------------------------------------------------------------------------
// GEMM + bias: C[M,1024] = A[M,1024] @ W[1024,1024] + b
// 64x64 block tile, BK=16, 256 threads, 4x4 microtile, float4 everywhere.
// ---------------------------------------------------------------------------
__global__ void __launch_bounds__(256) gemm_bias_kernel(
    const float* __restrict__ A,
    const float* __restrict__ W,
    const float* __restrict__ bias,
    float* __restrict__ C)
{
    constexpr int N = E_;
    constexpr int K = E_;
    __shared__ __align__(16) float As[16][68];   // As[k][m], padded
    __shared__ __align__(16) float Bs[16][64];   // Bs[k][n]

    const int tid = threadIdx.x;
    const int tx = tid & 15;          // 0..15 -> n microtile
    const int ty = tid >> 4;          // 0..15 -> m microtile
    const int m0 = blockIdx.y * 64;
    const int n0 = blockIdx.x * 64;

    // loader indices
    const int lm  = tid >> 2;         // 0..63 A row
    const int lk4 = tid & 3;          // 0..3  A k-float4
    const int lbk = tid >> 4;         // 0..15 W row
    const int lbn4 = tid & 15;        // 0..15 W n-float4

    float acc[4][4] = {};

    for (int k0 = 0; k0 < K; k0 += 16) {
        float4 a4 = *(const float4*)&A[(size_t)(m0 + lm) * K + k0 + lk4 * 4];
        As[lk4 * 4 + 0][lm] = a4.x;
        As[lk4 * 4 + 1][lm] = a4.y;
        As[lk4 * 4 + 2][lm] = a4.z;
        As[lk4 * 4 + 3][lm] = a4.w;
        *(float4*)&Bs[lbk][lbn4 * 4] =
            *(const float4*)&W[(size_t)(k0 + lbk) * N + n0 + lbn4 * 4];
        __syncthreads();

        #pragma unroll
        for (int k = 0; k < 16; k++) {
            float4 av = *(const float4*)&As[k][ty << 2];
            float4 bv = *(const float4*)&Bs[k][tx << 2];
            float ar[4] = {av.x, av.y, av.z, av.w};
            float br[4] = {bv.x, bv.y, bv.z, bv.w};
            #pragma unroll
            for (int i = 0; i < 4; i++)
                #pragma unroll
                for (int j = 0; j < 4; j++)
                    acc[i][j] += ar[i] * br[j];
        }
        __syncthreads();
    }

    float4 bb = *(const float4*)&bias[n0 + tx * 4];
    float bvr[4] = {bb.x, bb.y, bb.z, bb.w};
    #pragma unroll
    for (int i = 0; i < 4; i++) {
        int row = m0 + ty * 4 + i;
        float4 o;
        o.x = acc[i][0] + bvr[0];
        o.y = acc[i][1] + bvr[1];
        o.z = acc[i][2] + bvr[2];
        o.w = acc[i][3] + bvr[3];
        *(float4*)&C[(size_t)row * N + n0 + tx * 4] = o;
    }
}

// ---------------------------------------------------------------------------
// Flash-style attention. One block = 64 query rows of one (b,h).
// 256 threads: row = tid/4 (query row 0..63), part = tid%4 (16 d-cols each).
// Online softmax over 32 KV tiles of 64. K-tile and P-tile share smem.
// XOR swizzle at float4 granularity -> conflict-free, zero pad, 48KB exact.
// ---------------------------------------------------------------------------
__device__ __forceinline__ int swz(int a, int b) {
    // layout: row index a (stride 64 floats), inner index b permuted in groups of 4
    return a * 64 + ((((b >> 2) ^ (a & 15)) << 2) | (b & 3));
}

__global__ void __launch_bounds__(256) attn_kernel(
    const float* __restrict__ Q,
    const float* __restrict__ K,
    const float* __restrict__ V,
    float* __restrict__ O)
{
    __shared__ __align__(16) float Qst[64 * 64];  // [kk][row] swizzled
    __shared__ __align__(16) float KPs[64 * 64];  // K: [kk][j] swizzled; later P: [row][j] swizzled
    __shared__ __align__(16) float Vs[64 * 64];   // [j][d] natural

    const int tid  = threadIdx.x;
    const int row  = tid >> 2;        // query row within tile
    const int part = tid & 3;         // d/j quarter
    const int q0   = blockIdx.x * 64;
    const int bh   = blockIdx.y;
    const int b    = bh >> 4;
    const int h    = bh & 15;

    const float* Qg = Q + (size_t)(b * S_ + q0) * E_ + h * D_;

    // load Q tile transposed+swizzled
    #pragma unroll
    for (int i = 0; i < 16; i++) {
        int idx = tid + i * 256;
        int r = idx >> 6;             // query row
        int c = idx & 63;             // d
        Qst[swz(c, r)] = Qg[(size_t)r * E_ + c];
    }

    float m_run = -1e30f;
    float l_run = 0.f;
    float acc[16] = {};

    for (int t = 0; t < S_ / 64; t++) {
        const float* Kg = K + (size_t)(b * S_ + t * 64) * E_ + h * D_;
        const float* Vg = V + (size_t)(b * S_ + t * 64) * E_ + h * D_;

        __syncthreads();   // previous tile's P/V reads done (also covers Q stores at t=0)
        #pragma unroll
        for (int i = 0; i < 16; i++) {
            int idx = tid + i * 256;
            int r = idx >> 6;         // kv row j
            int c = idx & 63;         // d / kk
            KPs[swz(c, r)] = Kg[(size_t)r * E_ + c];
            Vs[r * 64 + c] = Vg[(size_t)r * E_ + c];
        }
        __syncthreads();

        // S = Q K^T for my (row, 16 j-cols)
        float s[16] = {};
        #pragma unroll 8
        for (int kk = 0; kk < 64; kk++) {
            float qv = Qst[swz(kk, row)];
            const float* kr = &KPs[kk * 64];
            int msk = kk & 15;
            #pragma unroll
            for (int jj4 = 0; jj4 < 4; jj4++) {
                int gp = (part * 4 + jj4) ^ msk;   // physical float4 group
                float4 kv = *(const float4*)&kr[gp * 4];
                s[jj4 * 4 + 0] += qv * kv.x;
                s[jj4 * 4 + 1] += qv * kv.y;
                s[jj4 * 4 + 2] += qv * kv.z;
                s[jj4 * 4 + 3] += qv * kv.w;
            }
        }

        // online softmax (4 threads per row cooperate via shfl)
        float mt = -1e30f;
        #pragma unroll
        for (int i = 0; i < 16; i++) { s[i] *= 0.125f; mt = fmaxf(mt, s[i]); }
        mt = fmaxf(mt, __shfl_xor_sync(0xffffffffu, mt, 1));
        mt = fmaxf(mt, __shfl_xor_sync(0xffffffffu, mt, 2));
        float m_new = fmaxf(m_run, mt);
        float corr  = __expf(m_run - m_new);
        float lt = 0.f;
        #pragma unroll
        for (int i = 0; i < 16; i++) { s[i] = __expf(s[i] - m_new); lt += s[i]; }
        lt += __shfl_xor_sync(0xffffffffu, lt, 1);
        lt += __shfl_xor_sync(0xffffffffu, lt, 2);
        l_run = l_run * corr + lt;
        m_run = m_new;
        #pragma unroll
        for (int i = 0; i < 16; i++) acc[i] *= corr;

        __syncthreads();   // all K reads done, safe to overwrite with P
        {
            int msk = row & 15;
            #pragma unroll
            for (int jj4 = 0; jj4 < 4; jj4++) {
                int gp = (part * 4 + jj4) ^ msk;
                float4 pv = make_float4(s[jj4 * 4 + 0], s[jj4 * 4 + 1],
                                        s[jj4 * 4 + 2], s[jj4 * 4 + 3]);
                *(float4*)&KPs[row * 64 + gp * 4] = pv;
            }
        }
        __syncthreads();

        // O += P @ V for my (row, 16 d-cols)
        #pragma unroll 8
        for (int j = 0; j < 64; j++) {
            float pv = KPs[swz(row, j)];
            const float4* vp = (const float4*)&Vs[j * 64 + part * 16];
            float4 v0 = vp[0], v1 = vp[1], v2 = vp[2], v3 = vp[3];
            acc[0]  += pv * v0.x;  acc[1]  += pv * v0.y;
            acc[2]  += pv * v0.z;  acc[3]  += pv * v0.w;
            acc[4]  += pv * v1.x;  acc[5]  += pv * v1.y;
            acc[6]  += pv * v1.z;  acc[7]  += pv * v1.w;
            acc[8]  += pv * v2.x;  acc[9]  += pv * v2.y;
            acc[10] += pv * v2.z;  acc[11] += pv * v2.w;
            acc[12] += pv * v3.x;  acc[13] += pv * v3.y;
            acc[14] += pv * v3.z;  acc[15] += pv * v3.w;
        }
    }

    float inv = 1.f / l_run;
    float* Og = O + (size_t)(b * S_ + q0 + row) * E_ + h * D_ + part * 16;
    #pragma unroll
    for (int g = 0; g < 4; g++) {
        float4 o;
        o.x = acc[g * 4 + 0] * inv;
        o.y = acc[g * 4 + 1] * inv;
        o.z = acc[g * 4 + 2] * inv;
        o.w = acc[g * 4 + 3] * inv;
        *(float4*)&Og[g * 4] = o;
    }
}

// ---------------------------------------------------------------------------
extern "C" void kernel_launch(void* const* d_in, const int* in_sizes, int n_in,
                              void* d_out, int out_size)
{
    const float* value = (const float*)d_in[0];
    const float* key_  = (const float*)d_in[1];
    const float* query = (const float*)d_in[2];
    const float* Wv = (const float*)d_in[3];
    const float* bv = (const float*)d_in[4];
    const float* Wk = (const float*)d_in[5];
    const float* bk = (const float*)d_in[6];
    const float* Wq = (const float*)d_in[7];
    const float* bq = (const float*)d_in[8];
    const float* Wo = (const float*)d_in[9];
    const float* bo = (const float*)d_in[10];
    float* out = (float*)d_out;

    float *gq, *gk, *gv, *go;
    cudaGetSymbolAddress((void**)&gq, g_Q);
    cudaGetSymbolAddress((void**)&gk, g_K);
    cudaGetSymbolAddress((void**)&gv, g_V);
    cudaGetSymbolAddress((void**)&go, g_O);

    dim3 blk(256);
    dim3 gg(E_ / 64, M_ / 64);   // (16, 128)

    gemm_bias_kernel<<<gg, blk>>>(value, Wv, bv, gv);
    gemm_bias_kernel<<<gg, blk>>>(key_,  Wk, bk, gk);
    gemm_bias_kernel<<<gg, blk>>>(query, Wq, bq, gq);

    attn_kernel<<<dim3(S_ / 64, B_ * H_), blk>>>(gq, gk, gv, go);

    gemm_bias_kernel<<<gg, blk>>>(go, Wo, bo, out);
}

// round 2
// speedup vs baseline: 1.0002x; 1.0002x over previous
#include <cuda_runtime.h>
#include <cstdint>

// ---------------------------------------------------------------------------
// MultiHeadAttention: B=4, S=2048, E=1024, H=16, D=64, fp32
// out = softmax((q@Wq+bq)(k@Wk+bk)^T / 8) @ (v@Wv+bv) @ Wo + bo
// ---------------------------------------------------------------------------

#define B_    4
#define S_    2048
#define E_    1024
#define H_    16
#define D_    64
#define M_    (B_ * S_)          // 8192 rows for all projections

// Scratch (device globals -- no allocation allowed)
__device__ float g_Q[M_ * E_];
__device__ float g_K[M_ * E_];
__device__ float g_V[M_ * E_];
__device__ float g_O[M_ * E_];

// ---------------------------------------------------------------------------
// GEMM + bias: C[M,1024] = A[M,1024] @ W[1024,1024] + b
// 64x64 block tile, BK=16, 256 threads, 4x4 microtile, float4 everywhere.
// ---------------------------------------------------------------------------
__global__ void __launch_bounds__(256) gemm_bias_kernel(
    const float* __restrict__ A,
    const float* __restrict__ W,
    const float* __restrict__ bias,
    float* __restrict__ C)
{
    constexpr int N = E_;
    constexpr int K = E_;
    __shared__ __align__(16) float As[16][68];   // As[k][m], padded
    __shared__ __align__(16) float Bs[16][64];   // Bs[k][n]

    const int tid = threadIdx.x;
    const int tx = tid & 15;          // 0..15 -> n microtile
    const int ty = tid >> 4;          // 0..15 -> m microtile
    const int m0 = blockIdx.y * 64;
    const int n0 = blockIdx.x * 64;

    // loader indices
    const int lm  = tid >> 2;         // 0..63 A row
    const int lk4 = tid & 3;          // 0..3  A k-float4
    const int lbk = tid >> 4;         // 0..15 W row
    const int lbn4 = tid & 15;        // 0..15 W n-float4

    float acc[4][4] = {};

    for (int k0 = 0; k0 < K; k0 += 16) {
        float4 a4 = *(const float4*)&A[(size_t)(m0 + lm) * K + k0 + lk4 * 4];
        As[lk4 * 4 + 0][lm] = a4.x;
        As[lk4 * 4 + 1][lm] = a4.y;
        As[lk4 * 4 + 2][lm] = a4.z;
        As[lk4 * 4 + 3][lm] = a4.w;
        *(float4*)&Bs[lbk][lbn4 * 4] =
            *(const float4*)&W[(size_t)(k0 + lbk) * N + n0 + lbn4 * 4];
        __syncthreads();

        #pragma unroll
        for (int k = 0; k < 16; k++) {
            float4 av = *(const float4*)&As[k][ty << 2];
            float4 bv = *(const float4*)&Bs[k][tx << 2];
            float ar[4] = {av.x, av.y, av.z, av.w};
            float br[4] = {bv.x, bv.y, bv.z, bv.w};
            #pragma unroll
            for (int i = 0; i < 4; i++)
                #pragma unroll
                for (int j = 0; j < 4; j++)
                    acc[i][j] += ar[i] * br[j];
        }
        __syncthreads();
    }

    float4 bb = *(const float4*)&bias[n0 + tx * 4];
    float bvr[4] = {bb.x, bb.y, bb.z, bb.w};
    #pragma unroll
    for (int i = 0; i < 4; i++) {
        int row = m0 + ty * 4 + i;
        float4 o;
        o.x = acc[i][0] + bvr[0];
        o.y = acc[i][1] + bvr[1];
        o.z = acc[i][2] + bvr[2];
        o.w = acc[i][3] + bvr[3];
        *(float4*)&C[(size_t)row * N + n0 + tx * 4] = o;
    }
}

// ---------------------------------------------------------------------------
// Flash-style attention. One block = 64 query rows of one (b,h).
// 256 threads: row = tid/4 (query row 0..63), part = tid%4 (16 d-cols each).
// Online softmax over 32 KV tiles of 64. K-tile and P-tile share smem.
// XOR swizzle at float4 granularity -> conflict-free, zero pad, 48KB exact.
// ---------------------------------------------------------------------------
__device__ __forceinline__ int swz(int a, int b) {
    // layout: row index a (stride 64 floats), inner index b permuted in groups of 4
    return a * 64 + ((((b >> 2) ^ (a & 15)) << 2) | (b & 3));
}

__global__ void __launch_bounds__(256) attn_kernel(
    const float* __restrict__ Q,
    const float* __restrict__ K,
    const float* __restrict__ V,
    float* __restrict__ O)
{
    __shared__ __align__(16) float Qst[64 * 64];  // [kk][row] swizzled
    __shared__ __align__(16) float KPs[64 * 64];  // K: [kk][j] swizzled; later P: [row][j] swizzled
    __shared__ __align__(16) float Vs[64 * 64];   // [j][d] natural

    const int tid  = threadIdx.x;
    const int row  = tid >> 2;        // query row within tile
    const int part = tid & 3;         // d/j quarter
    const int q0   = blockIdx.x * 64;
    const int bh   = blockIdx.y;
    const int b    = bh >> 4;
    const int h    = bh & 15;

    const float* Qg = Q + (size_t)(b * S_ + q0) * E_ + h * D_;

    // load Q tile transposed+swizzled
    #pragma unroll
    for (int i = 0; i < 16; i++) {
        int idx = tid + i * 256;
        int r = idx >> 6;             // query row
        int c = idx & 63;             // d
        Qst[swz(c, r)] = Qg[(size_t)r * E_ + c];
    }

    float m_run = -1e30f;
    float l_run = 0.f;
    float acc[16] = {};

    for (int t = 0; t < S_ / 64; t++) {
        const float* Kg = K + (size_t)(b * S_ + t * 64) * E_ + h * D_;
        const float* Vg = V + (size_t)(b * S_ + t * 64) * E_ + h * D_;

        __syncthreads();   // previous tile's P/V reads done (also covers Q stores at t=0)
        #pragma unroll
        for (int i = 0; i < 16; i++) {
            int idx = tid + i * 256;
            int r = idx >> 6;         // kv row j
            int c = idx & 63;         // d / kk
            KPs[swz(c, r)] = Kg[(size_t)r * E_ + c];
            Vs[r * 64 + c] = Vg[(size_t)r * E_ + c];
        }
        __syncthreads();

        // S = Q K^T for my (row, 16 j-cols)
        float s[16] = {};
        #pragma unroll 8
        for (int kk = 0; kk < 64; kk++) {
            float qv = Qst[swz(kk, row)];
            const float* kr = &KPs[kk * 64];
            int msk = kk & 15;
            #pragma unroll
            for (int jj4 = 0; jj4 < 4; jj4++) {
                int gp = (part * 4 + jj4) ^ msk;   // physical float4 group
                float4 kv = *(const float4*)&kr[gp * 4];
                s[jj4 * 4 + 0] += qv * kv.x;
                s[jj4 * 4 + 1] += qv * kv.y;
                s[jj4 * 4 + 2] += qv * kv.z;
                s[jj4 * 4 + 3] += qv * kv.w;
            }
        }

        // online softmax (4 threads per row cooperate via shfl)
        float mt = -1e30f;
        #pragma unroll
        for (int i = 0; i < 16; i++) { s[i] *= 0.125f; mt = fmaxf(mt, s[i]); }
        mt = fmaxf(mt, __shfl_xor_sync(0xffffffffu, mt, 1));
        mt = fmaxf(mt, __shfl_xor_sync(0xffffffffu, mt, 2));
        float m_new = fmaxf(m_run, mt);
        float corr  = __expf(m_run - m_new);
        float lt = 0.f;
        #pragma unroll
        for (int i = 0; i < 16; i++) { s[i] = __expf(s[i] - m_new); lt += s[i]; }
        lt += __shfl_xor_sync(0xffffffffu, lt, 1);
        lt += __shfl_xor_sync(0xffffffffu, lt, 2);
        l_run = l_run * corr + lt;
        m_run = m_new;
        #pragma unroll
        for (int i = 0; i < 16; i++) acc[i] *= corr;

        __syncthreads();   // all K reads done, safe to overwrite with P
        {
            int msk = row & 15;
            #pragma unroll
            for (int jj4 = 0; jj4 < 4; jj4++) {
                int gp = (part * 4 + jj4) ^ msk;
                float4 pv = make_float4(s[jj4 * 4 + 0], s[jj4 * 4 + 1],
                                        s[jj4 * 4 + 2], s[jj4 * 4 + 3]);
                *(float4*)&KPs[row * 64 + gp * 4] = pv;
            }
        }
        __syncthreads();

        // O += P @ V for my (row, 16 d-cols)
        #pragma unroll 8
        for (int j = 0; j < 64; j++) {
            float pv = KPs[swz(row, j)];
            const float4* vp = (const float4*)&Vs[j * 64 + part * 16];
            float4 v0 = vp[0], v1 = vp[1], v2 = vp[2], v3 = vp[3];
            acc[0]  += pv * v0.x;  acc[1]  += pv * v0.y;
            acc[2]  += pv * v0.z;  acc[3]  += pv * v0.w;
            acc[4]  += pv * v1.x;  acc[5]  += pv * v1.y;
            acc[6]  += pv * v1.z;  acc[7]  += pv * v1.w;
            acc[8]  += pv * v2.x;  acc[9]  += pv * v2.y;
            acc[10] += pv * v2.z;  acc[11] += pv * v2.w;
            acc[12] += pv * v3.x;  acc[13] += pv * v3.y;
            acc[14] += pv * v3.z;  acc[15] += pv * v3.w;
        }
    }

    float inv = 1.f / l_run;
    float* Og = O + (size_t)(b * S_ + q0 + row) * E_ + h * D_ + part * 16;
    #pragma unroll
    for (int g = 0; g < 4; g++) {
        float4 o;
        o.x = acc[g * 4 + 0] * inv;
        o.y = acc[g * 4 + 1] * inv;
        o.z = acc[g * 4 + 2] * inv;
        o.w = acc[g * 4 + 3] * inv;
        *(float4*)&Og[g * 4] = o;
    }
}

// ---------------------------------------------------------------------------
extern "C" void kernel_launch(void* const* d_in, const int* in_sizes, int n_in,
                              void* d_out, int out_size)
{
    const float* value = (const float*)d_in[0];
    const float* key_  = (const float*)d_in[1];
    const float* query = (const float*)d_in[2];
    const float* Wv = (const float*)d_in[3];
    const float* bv = (const float*)d_in[4];
    const float* Wk = (const float*)d_in[5];
    const float* bk = (const float*)d_in[6];
    const float* Wq = (const float*)d_in[7];
    const float* bq = (const float*)d_in[8];
    const float* Wo = (const float*)d_in[9];
    const float* bo = (const float*)d_in[10];
    float* out = (float*)d_out;

    float *gq, *gk, *gv, *go;
    cudaGetSymbolAddress((void**)&gq, g_Q);
    cudaGetSymbolAddress((void**)&gk, g_K);
    cudaGetSymbolAddress((void**)&gv, g_V);
    cudaGetSymbolAddress((void**)&go, g_O);

    dim3 blk(256);
    dim3 gg(E_ / 64, M_ / 64);   // (16, 128)

    gemm_bias_kernel<<<gg, blk>>>(value, Wv, bv, gv);
    gemm_bias_kernel<<<gg, blk>>>(key_,  Wk, bk, gk);
    gemm_bias_kernel<<<gg, blk>>>(query, Wq, bq, gq);

    attn_kernel<<<dim3(S_ / 64, B_ * H_), blk>>>(gq, gk, gv, go);

    gemm_bias_kernel<<<gg, blk>>>(go, Wo, bo, out);
}

// round 3
// speedup vs baseline: 1.0004x; 1.0002x over previous
#include <cuda_runtime.h>
#include <cstdint>

// ---------------------------------------------------------------------------
// MultiHeadAttention: B=4, S=2048, E=1024, H=16, D=64, fp32
// out = softmax((q@Wq+bq)(k@Wk+bk)^T / 8) @ (v@Wv+bv) @ Wo + bo
// ---------------------------------------------------------------------------

#define B_    4
#define S_    2048
#define E_    1024
#define H_    16
#define D_    64
#define M_    (B_ * S_)          // 8192 rows for all projections

// Scratch (device globals -- no allocation allowed)
__device__ float g_Q[M_ * E_];
__device__ float g_K[M_ * E_];
__device__ float g_V[M_ * E_];
__device__ float g_O[M_ * E_];

// ---------------------------------------------------------------------------
// GEMM + bias: C[M,1024] = A[M,1024] @ W[1024,1024] + b
// 64x64 block tile, BK=16, 256 threads, 4x4 microtile, float4 everywhere.
// ---------------------------------------------------------------------------
__global__ void __launch_bounds__(256) gemm_bias_kernel(
    const float* __restrict__ A,
    const float* __restrict__ W,
    const float* __restrict__ bias,
    float* __restrict__ C)
{
    constexpr int N = E_;
    constexpr int K = E_;
    __shared__ __align__(16) float As[16][68];   // As[k][m], padded
    __shared__ __align__(16) float Bs[16][64];   // Bs[k][n]

    const int tid = threadIdx.x;
    const int tx = tid & 15;          // 0..15 -> n microtile
    const int ty = tid >> 4;          // 0..15 -> m microtile
    const int m0 = blockIdx.y * 64;
    const int n0 = blockIdx.x * 64;

    // loader indices
    const int lm  = tid >> 2;         // 0..63 A row
    const int lk4 = tid & 3;          // 0..3  A k-float4
    const int lbk = tid >> 4;         // 0..15 W row
    const int lbn4 = tid & 15;        // 0..15 W n-float4

    float acc[4][4] = {};

    for (int k0 = 0; k0 < K; k0 += 16) {
        float4 a4 = *(const float4*)&A[(size_t)(m0 + lm) * K + k0 + lk4 * 4];
        As[lk4 * 4 + 0][lm] = a4.x;
        As[lk4 * 4 + 1][lm] = a4.y;
        As[lk4 * 4 + 2][lm] = a4.z;
        As[lk4 * 4 + 3][lm] = a4.w;
        *(float4*)&Bs[lbk][lbn4 * 4] =
            *(const float4*)&W[(size_t)(k0 + lbk) * N + n0 + lbn4 * 4];
        __syncthreads();

        #pragma unroll
        for (int k = 0; k < 16; k++) {
            float4 av = *(const float4*)&As[k][ty << 2];
            float4 bv = *(const float4*)&Bs[k][tx << 2];
            float ar[4] = {av.x, av.y, av.z, av.w};
            float br[4] = {bv.x, bv.y, bv.z, bv.w};
            #pragma unroll
            for (int i = 0; i < 4; i++)
                #pragma unroll
                for (int j = 0; j < 4; j++)
                    acc[i][j] += ar[i] * br[j];
        }
        __syncthreads();
    }

    float4 bb = *(const float4*)&bias[n0 + tx * 4];
    float bvr[4] = {bb.x, bb.y, bb.z, bb.w};
    #pragma unroll
    for (int i = 0; i < 4; i++) {
        int row = m0 + ty * 4 + i;
        float4 o;
        o.x = acc[i][0] + bvr[0];
        o.y = acc[i][1] + bvr[1];
        o.z = acc[i][2] + bvr[2];
        o.w = acc[i][3] + bvr[3];
        *(float4*)&C[(size_t)row * N + n0 + tx * 4] = o;
    }
}

// ---------------------------------------------------------------------------
// Flash-style attention. One block = 64 query rows of one (b,h).
// 256 threads: row = tid/4 (query row 0..63), part = tid%4 (16 d-cols each).
// Online softmax over 32 KV tiles of 64. K-tile and P-tile share smem.
// XOR swizzle at float4 granularity -> conflict-free, zero pad, 48KB exact.
// ---------------------------------------------------------------------------
__device__ __forceinline__ int swz(int a, int b) {
    // layout: row index a (stride 64 floats), inner index b permuted in groups of 4
    return a * 64 + ((((b >> 2) ^ (a & 15)) << 2) | (b & 3));
}

__global__ void __launch_bounds__(256) attn_kernel(
    const float* __restrict__ Q,
    const float* __restrict__ K,
    const float* __restrict__ V,
    float* __restrict__ O)
{
    __shared__ __align__(16) float Qst[64 * 64];  // [kk][row] swizzled
    __shared__ __align__(16) float KPs[64 * 64];  // K: [kk][j] swizzled; later P: [row][j] swizzled
    __shared__ __align__(16) float Vs[64 * 64];   // [j][d] natural

    const int tid  = threadIdx.x;
    const int row  = tid >> 2;        // query row within tile
    const int part = tid & 3;         // d/j quarter
    const int q0   = blockIdx.x * 64;
    const int bh   = blockIdx.y;
    const int b    = bh >> 4;
    const int h    = bh & 15;

    const float* Qg = Q + (size_t)(b * S_ + q0) * E_ + h * D_;

    // load Q tile transposed+swizzled
    #pragma unroll
    for (int i = 0; i < 16; i++) {
        int idx = tid + i * 256;
        int r = idx >> 6;             // query row
        int c = idx & 63;             // d
        Qst[swz(c, r)] = Qg[(size_t)r * E_ + c];
    }

    float m_run = -1e30f;
    float l_run = 0.f;
    float acc[16] = {};

    for (int t = 0; t < S_ / 64; t++) {
        const float* Kg = K + (size_t)(b * S_ + t * 64) * E_ + h * D_;
        const float* Vg = V + (size_t)(b * S_ + t * 64) * E_ + h * D_;

        __syncthreads();   // previous tile's P/V reads done (also covers Q stores at t=0)
        #pragma unroll
        for (int i = 0; i < 16; i++) {
            int idx = tid + i * 256;
            int r = idx >> 6;         // kv row j
            int c = idx & 63;         // d / kk
            KPs[swz(c, r)] = Kg[(size_t)r * E_ + c];
            Vs[r * 64 + c] = Vg[(size_t)r * E_ + c];
        }
        __syncthreads();

        // S = Q K^T for my (row, 16 j-cols)
        float s[16] = {};
        #pragma unroll 8
        for (int kk = 0; kk < 64; kk++) {
            float qv = Qst[swz(kk, row)];
            const float* kr = &KPs[kk * 64];
            int msk = kk & 15;
            #pragma unroll
            for (int jj4 = 0; jj4 < 4; jj4++) {
                int gp = (part * 4 + jj4) ^ msk;   // physical float4 group
                float4 kv = *(const float4*)&kr[gp * 4];
                s[jj4 * 4 + 0] += qv * kv.x;
                s[jj4 * 4 + 1] += qv * kv.y;
                s[jj4 * 4 + 2] += qv * kv.z;
                s[jj4 * 4 + 3] += qv * kv.w;
            }
        }

        // online softmax (4 threads per row cooperate via shfl)
        float mt = -1e30f;
        #pragma unroll
        for (int i = 0; i < 16; i++) { s[i] *= 0.125f; mt = fmaxf(mt, s[i]); }
        mt = fmaxf(mt, __shfl_xor_sync(0xffffffffu, mt, 1));
        mt = fmaxf(mt, __shfl_xor_sync(0xffffffffu, mt, 2));
        float m_new = fmaxf(m_run, mt);
        float corr  = __expf(m_run - m_new);
        float lt = 0.f;
        #pragma unroll
        for (int i = 0; i < 16; i++) { s[i] = __expf(s[i] - m_new); lt += s[i]; }
        lt += __shfl_xor_sync(0xffffffffu, lt, 1);
        lt += __shfl_xor_sync(0xffffffffu, lt, 2);
        l_run = l_run * corr + lt;
        m_run = m_new;
        #pragma unroll
        for (int i = 0; i < 16; i++) acc[i] *= corr;

        __syncthreads();   // all K reads done, safe to overwrite with P
        {
            int msk = row & 15;
            #pragma unroll
            for (int jj4 = 0; jj4 < 4; jj4++) {
                int gp = (part * 4 + jj4) ^ msk;
                float4 pv = make_float4(s[jj4 * 4 + 0], s[jj4 * 4 + 1],
                                        s[jj4 * 4 + 2], s[jj4 * 4 + 3]);
                *(float4*)&KPs[row * 64 + gp * 4] = pv;
            }
        }
        __syncthreads();

        // O += P @ V for my (row, 16 d-cols)
        #pragma unroll 8
        for (int j = 0; j < 64; j++) {
            float pv = KPs[swz(row, j)];
            const float4* vp = (const float4*)&Vs[j * 64 + part * 16];
            float4 v0 = vp[0], v1 = vp[1], v2 = vp[2], v3 = vp[3];
            acc[0]  += pv * v0.x;  acc[1]  += pv * v0.y;
            acc[2]  += pv * v0.z;  acc[3]  += pv * v0.w;
            acc[4]  += pv * v1.x;  acc[5]  += pv * v1.y;
            acc[6]  += pv * v1.z;  acc[7]  += pv * v1.w;
            acc[8]  += pv * v2.x;  acc[9]  += pv * v2.y;
            acc[10] += pv * v2.z;  acc[11] += pv * v2.w;
            acc[12] += pv * v3.x;  acc[13] += pv * v3.y;
            acc[14] += pv * v3.z;  acc[15] += pv * v3.w;
        }
    }

    float inv = 1.f / l_run;
    float* Og = O + (size_t)(b * S_ + q0 + row) * E_ + h * D_ + part * 16;
    #pragma unroll
    for (int g = 0; g < 4; g++) {
        float4 o;
        o.x = acc[g * 4 + 0] * inv;
        o.y = acc[g * 4 + 1] * inv;
        o.z = acc[g * 4 + 2] * inv;
        o.w = acc[g * 4 + 3] * inv;
        *(float4*)&Og[g * 4] = o;
    }
}

// ---------------------------------------------------------------------------
extern "C" void kernel_launch(void* const* d_in, const int* in_sizes, int n_in,
                              void* d_out, int out_size)
{
    const float* value = (const float*)d_in[0];
    const float* key_  = (const float*)d_in[1];
    const float* query = (const float*)d_in[2];
    const float* Wv = (const float*)d_in[3];
    const float* bv = (const float*)d_in[4];
    const float* Wk = (const float*)d_in[5];
    const float* bk = (const float*)d_in[6];
    const float* Wq = (const float*)d_in[7];
    const float* bq = (const float*)d_in[8];
    const float* Wo = (const float*)d_in[9];
    const float* bo = (const float*)d_in[10];
    float* out = (float*)d_out;

    float *gq, *gk, *gv, *go;
    cudaGetSymbolAddress((void**)&gq, g_Q);
    cudaGetSymbolAddress((void**)&gk, g_K);
    cudaGetSymbolAddress((void**)&gv, g_V);
    cudaGetSymbolAddress((void**)&go, g_O);

    dim3 blk(256);
    dim3 gg(E_ / 64, M_ / 64);   // (16, 128)

    gemm_bias_kernel<<<gg, blk>>>(value, Wv, bv, gv);
    gemm_bias_kernel<<<gg, blk>>>(key_,  Wk, bk, gk);
    gemm_bias_kernel<<<gg, blk>>>(query, Wq, bq, gq);

    attn_kernel<<<dim3(S_ / 64, B_ * H_), blk>>>(gq, gk, gv, go);

    gemm_bias_kernel<<<gg, blk>>>(go, Wo, bo, out);
}

// round 5
// speedup vs baseline: 2.7683x; 2.7673x over previous
#include <cuda_runtime.h>
#include <cstdint>

// ---------------------------------------------------------------------------
// MultiHeadAttention: B=4, S=2048, E=1024, H=16, D=64, fp32
// out = softmax((q@Wq+bq)(k@Wk+bk)^T / 8) @ (v@Wv+bv) @ Wo + bo
// ---------------------------------------------------------------------------

#define B_    4
#define S_    2048
#define E_    1024
#define H_    16
#define D_    64
#define M_    (B_ * S_)          // 8192 rows for all projections

// Scratch (device globals -- no allocation allowed)
// Qt/Kt hold the projections TRANSPOSED: layout [(b*16+h)*64 + d][s] (stride S_)
__device__ float g_Qt[M_ * E_];
__device__ float g_Kt[M_ * E_];
__device__ float g_V [M_ * E_];
__device__ float g_O [M_ * E_];

// ---------------------------------------------------------------------------
// GEMM + bias: C[M,1024] = A[M,1024] @ W[1024,1024] + b   (normal layout)
// 64x64 block tile, BK=16, 256 threads, 4x4 microtile, float4 everywhere.
// ---------------------------------------------------------------------------
__global__ void __launch_bounds__(256) gemm_bias_kernel(
    const float* __restrict__ A,
    const float* __restrict__ W,
    const float* __restrict__ bias,
    float* __restrict__ C)
{
    constexpr int N = E_;
    constexpr int K = E_;
    __shared__ __align__(16) float As[16][68];   // As[k][m], padded
    __shared__ __align__(16) float Bs[16][64];   // Bs[k][n]

    const int tid = threadIdx.x;
    const int tx = tid & 15;          // n microtile
    const int ty = tid >> 4;          // m microtile
    const int m0 = blockIdx.y * 64;
    const int n0 = blockIdx.x * 64;

    const int lm  = tid >> 2;
    const int lk4 = tid & 3;
    const int lbk = tid >> 4;
    const int lbn4 = tid & 15;

    float acc[4][4] = {};

    for (int k0 = 0; k0 < K; k0 += 16) {
        float4 a4 = *(const float4*)&A[(size_t)(m0 + lm) * K + k0 + lk4 * 4];
        As[lk4 * 4 + 0][lm] = a4.x;
        As[lk4 * 4 + 1][lm] = a4.y;
        As[lk4 * 4 + 2][lm] = a4.z;
        As[lk4 * 4 + 3][lm] = a4.w;
        *(float4*)&Bs[lbk][lbn4 * 4] =
            *(const float4*)&W[(size_t)(k0 + lbk) * N + n0 + lbn4 * 4];
        __syncthreads();

        #pragma unroll
        for (int k = 0; k < 16; k++) {
            float4 av = *(const float4*)&As[k][ty << 2];
            float4 bv = *(const float4*)&Bs[k][tx << 2];
            float ar[4] = {av.x, av.y, av.z, av.w};
            float br[4] = {bv.x, bv.y, bv.z, bv.w};
            #pragma unroll
            for (int i = 0; i < 4; i++)
                #pragma unroll
                for (int j = 0; j < 4; j++)
                    acc[i][j] += ar[i] * br[j];
        }
        __syncthreads();
    }

    float4 bb = *(const float4*)&bias[n0 + tx * 4];
    float bvr[4] = {bb.x, bb.y, bb.z, bb.w};
    #pragma unroll
    for (int i = 0; i < 4; i++) {
        int row = m0 + ty * 4 + i;
        float4 o;
        o.x = acc[i][0] + bvr[0];
        o.y = acc[i][1] + bvr[1];
        o.z = acc[i][2] + bvr[2];
        o.w = acc[i][3] + bvr[3];
        *(float4*)&C[(size_t)row * N + n0 + tx * 4] = o;
    }
}

// ---------------------------------------------------------------------------
// Same GEMM but epilogue writes TRANSPOSED: Ct[(b*1024 + n)*2048 + s]
// (n = h*64+d contiguous over E_, s = row within batch). Used for Q and K so
// the attention kernel gets d-major, fully coalesced, swizzle-free tiles.
// ---------------------------------------------------------------------------
__global__ void __launch_bounds__(256) gemm_bias_T_kernel(
    const float* __restrict__ A,
    const float* __restrict__ W,
    const float* __restrict__ bias,
    float* __restrict__ Ct)
{
    constexpr int N = E_;
    constexpr int K = E_;
    __shared__ __align__(16) float As[16][68];
    __shared__ __align__(16) float Bs[16][64];

    const int tid = threadIdx.x;
    const int tx = tid & 15;
    const int ty = tid >> 4;
    const int m0 = blockIdx.y * 64;
    const int n0 = blockIdx.x * 64;

    const int lm  = tid >> 2;
    const int lk4 = tid & 3;
    const int lbk = tid >> 4;
    const int lbn4 = tid & 15;

    float acc[4][4] = {};

    for (int k0 = 0; k0 < K; k0 += 16) {
        float4 a4 = *(const float4*)&A[(size_t)(m0 + lm) * K + k0 + lk4 * 4];
        As[lk4 * 4 + 0][lm] = a4.x;
        As[lk4 * 4 + 1][lm] = a4.y;
        As[lk4 * 4 + 2][lm] = a4.z;
        As[lk4 * 4 + 3][lm] = a4.w;
        *(float4*)&Bs[lbk][lbn4 * 4] =
            *(const float4*)&W[(size_t)(k0 + lbk) * N + n0 + lbn4 * 4];
        __syncthreads();

        #pragma unroll
        for (int k = 0; k < 16; k++) {
            float4 av = *(const float4*)&As[k][ty << 2];
            float4 bv = *(const float4*)&Bs[k][tx << 2];
            float ar[4] = {av.x, av.y, av.z, av.w};
            float br[4] = {bv.x, bv.y, bv.z, bv.w};
            #pragma unroll
            for (int i = 0; i < 4; i++)
                #pragma unroll
                for (int j = 0; j < 4; j++)
                    acc[i][j] += ar[i] * br[j];
        }
        __syncthreads();
    }

    const int b    = m0 >> 11;        // /2048
    const int sloc = (m0 & 2047) + ty * 4;
    #pragma unroll
    for (int j = 0; j < 4; j++) {
        int n = n0 + tx * 4 + j;
        float bn = bias[n];
        float4 o;
        o.x = acc[0][j] + bn;
        o.y = acc[1][j] + bn;
        o.z = acc[2][j] + bn;
        o.w = acc[3][j] + bn;
        *(float4*)&Ct[((size_t)(b * 1024 + n) << 11) + sloc] = o;
    }
}

// ---------------------------------------------------------------------------
// Flash-style attention, register-blocked.
// Block = 128 query rows of one (b,h). 256 threads = 16(ty) x 16(tx).
// Thread microtile: 8 query rows (ty*8..+7) x 4 cols (tx*4..+3).
// KV processed in tiles of 64. Q tile resident (d-major), K tile d-major,
// V tile j-major, P reuses the K buffer as [q][j]. No swizzle anywhere:
// every smem row is contiguous and accessed contiguously / by broadcast.
// Smem: Q 32KB + KP 32KB + V 16KB = 80KB dynamic, 2 CTAs/SM.
// ---------------------------------------------------------------------------
__global__ void __launch_bounds__(256, 2) attn_kernel(
    const float* __restrict__ Qt,   // [(bh)*64 + d][s]
    const float* __restrict__ Kt,   // [(bh)*64 + d][s]
    const float* __restrict__ V,    // [b][s][h*64 + d]
    float* __restrict__ O)          // [b][s][h*64 + d]
{
    extern __shared__ __align__(16) float sm[];
    float* Qs  = sm;             // [64][128]  d-major, pre-scaled by 1/8
    float* KPs = sm + 8192;      // K: [64][64] d-major ; later P: [128][64]
    float* Vs  = sm + 16384;     // [64][64]   j-major

    const int tid = threadIdx.x;
    const int tx  = tid & 15;
    const int ty  = tid >> 4;
    const int q0  = blockIdx.x * 128;
    const int bh  = blockIdx.y;
    const int b   = bh >> 4;
    const int h   = bh & 15;

    const size_t qtBase = (size_t)bh * 64 * S_;   // row d stride S_

    // ---- load Q tile (transposed source -> contiguous), scale by 1/8 ----
    #pragma unroll
    for (int i = 0; i < 8; i++) {
        int linear = tid + i * 256;        // 0..2047 float4s
        int qf = linear & 31;              // float4 within 128 q
        int d  = linear >> 5;              // 0..63
        float4 v = *(const float4*)&Qt[qtBase + (size_t)d * S_ + q0 + qf * 4];
        v.x *= 0.125f; v.y *= 0.125f; v.z *= 0.125f; v.w *= 0.125f;
        ((float4*)Qs)[d * 32 + qf] = v;
    }

    float m_run[8], l_run[8], acc[8][4];
    #pragma unroll
    for (int r = 0; r < 8; r++) {
        m_run[r] = -1e30f; l_run[r] = 0.f;
        acc[r][0] = acc[r][1] = acc[r][2] = acc[r][3] = 0.f;
    }

    for (int t = 0; t < S_ / 64; t++) {
        const int j0 = t * 64;

        __syncthreads();   // prev tile's P/V reads done (covers Q stores at t=0)

        // ---- load K (d-major) and V (j-major) tiles, fully coalesced ----
        #pragma unroll
        for (int i = 0; i < 4; i++) {
            int linear = tid + i * 256;    // 0..1023 float4s
            int f = linear & 15;
            int r = linear >> 4;           // 0..63
            ((float4*)KPs)[r * 16 + f] =
                *(const float4*)&Kt[qtBase + (size_t)r * S_ + j0 + f * 4];
            ((float4*)Vs)[r * 16 + f] =
                *(const float4*)&V[((size_t)(b * S_ + j0 + r) << 10) + h * 64 + f * 4];
        }
        __syncthreads();

        // ---- S = (Q/8) K^T : 8x4 outer product per thread ----
        float s[8][4];
        #pragma unroll
        for (int r = 0; r < 8; r++) s[r][0] = s[r][1] = s[r][2] = s[r][3] = 0.f;

        {
            const float4* Q4 = (const float4*)Qs + ty * 2;
            const float4* K4 = (const float4*)KPs + tx;
            #pragma unroll 4
            for (int kk = 0; kk < 64; kk++) {
                float4 qa = Q4[kk * 32];
                float4 qb = Q4[kk * 32 + 1];
                float4 kv = K4[kk * 16];
                float qr[8] = {qa.x, qa.y, qa.z, qa.w, qb.x, qb.y, qb.z, qb.w};
                #pragma unroll
                for (int r = 0; r < 8; r++) {
                    s[r][0] += qr[r] * kv.x;
                    s[r][1] += qr[r] * kv.y;
                    s[r][2] += qr[r] * kv.z;
                    s[r][3] += qr[r] * kv.w;
                }
            }
        }

        // ---- online softmax (16 tx-threads per row cooperate) ----
        #pragma unroll
        for (int r = 0; r < 8; r++) {
            float mt = fmaxf(fmaxf(s[r][0], s[r][1]), fmaxf(s[r][2], s[r][3]));
            mt = fmaxf(mt, __shfl_xor_sync(0xffffffffu, mt, 1));
            mt = fmaxf(mt, __shfl_xor_sync(0xffffffffu, mt, 2));
            mt = fmaxf(mt, __shfl_xor_sync(0xffffffffu, mt, 4));
            mt = fmaxf(mt, __shfl_xor_sync(0xffffffffu, mt, 8));
            float m_new = fmaxf(m_run[r], mt);
            float corr  = __expf(m_run[r] - m_new);
            m_run[r] = m_new;
            float lt = 0.f;
            #pragma unroll
            for (int c = 0; c < 4; c++) {
                s[r][c] = __expf(s[r][c] - m_new);
                lt += s[r][c];
            }
            lt += __shfl_xor_sync(0xffffffffu, lt, 1);
            lt += __shfl_xor_sync(0xffffffffu, lt, 2);
            lt += __shfl_xor_sync(0xffffffffu, lt, 4);
            lt += __shfl_xor_sync(0xffffffffu, lt, 8);
            l_run[r] = l_run[r] * corr + lt;
            acc[r][0] *= corr; acc[r][1] *= corr;
            acc[r][2] *= corr; acc[r][3] *= corr;
        }

        __syncthreads();   // all K reads done; safe to overwrite with P

        // ---- store P[q][j] (contiguous float4 per thread) ----
        #pragma unroll
        for (int r = 0; r < 8; r++)
            ((float4*)KPs)[(ty * 8 + r) * 16 + tx] =
                make_float4(s[r][0], s[r][1], s[r][2], s[r][3]);
        __syncthreads();

        // ---- O += P @ V : 8x4 outer product per thread ----
        {
            const float4* V4 = (const float4*)Vs + tx;
            const float*  P  = KPs + ty * 8 * 64;
            #pragma unroll 2
            for (int j = 0; j < 64; j++) {
                float4 vv = V4[j * 16];
                #pragma unroll
                for (int r = 0; r < 8; r++) {
                    float p = P[r * 64 + j];     // 2-addr broadcast per warp
                    acc[r][0] += p * vv.x;
                    acc[r][1] += p * vv.y;
                    acc[r][2] += p * vv.z;
                    acc[r][3] += p * vv.w;
                }
            }
        }
    }

    // ---- normalize + write O (natural layout for the output GEMM) ----
    #pragma unroll
    for (int r = 0; r < 8; r++) {
        float inv = 1.f / l_run[r];
        float4 o;
        o.x = acc[r][0] * inv;
        o.y = acc[r][1] * inv;
        o.z = acc[r][2] * inv;
        o.w = acc[r][3] * inv;
        *(float4*)&O[((size_t)(b * S_ + q0 + ty * 8 + r) << 10) + h * 64 + tx * 4] = o;
    }
}

// ---------------------------------------------------------------------------
extern "C" void kernel_launch(void* const* d_in, const int* in_sizes, int n_in,
                              void* d_out, int out_size)
{
    const float* value = (const float*)d_in[0];
    const float* key_  = (const float*)d_in[1];
    const float* query = (const float*)d_in[2];
    const float* Wv = (const float*)d_in[3];
    const float* bv = (const float*)d_in[4];
    const float* Wk = (const float*)d_in[5];
    const float* bk = (const float*)d_in[6];
    const float* Wq = (const float*)d_in[7];
    const float* bq = (const float*)d_in[8];
    const float* Wo = (const float*)d_in[9];
    const float* bo = (const float*)d_in[10];
    float* out = (float*)d_out;

    float *gqt, *gkt, *gv, *go;
    cudaGetSymbolAddress((void**)&gqt, g_Qt);
    cudaGetSymbolAddress((void**)&gkt, g_Kt);
    cudaGetSymbolAddress((void**)&gv,  g_V);
    cudaGetSymbolAddress((void**)&go,  g_O);

    static int smem_set = 0;
    if (!smem_set) {
        cudaFuncSetAttribute(attn_kernel,
                             cudaFuncAttributeMaxDynamicSharedMemorySize,
                             20480 * sizeof(float));
        smem_set = 1;
    }

    dim3 blk(256);
    dim3 gg(E_ / 64, M_ / 64);   // (16, 128)

    gemm_bias_kernel  <<<gg, blk>>>(value, Wv, bv, gv);
    gemm_bias_T_kernel<<<gg, blk>>>(key_,  Wk, bk, gkt);
    gemm_bias_T_kernel<<<gg, blk>>>(query, Wq, bq, gqt);

    attn_kernel<<<dim3(S_ / 128, B_ * H_), blk, 20480 * sizeof(float)>>>(gqt, gkt, gv, go);

    gemm_bias_kernel<<<gg, blk>>>(go, Wo, bo, out);
}

// round 7
// speedup vs baseline: 4.2006x; 1.5174x over previous
#include <cuda_runtime.h>
#include <cuda_bf16.h>
#include <cstdint>

// ---------------------------------------------------------------------------
// MultiHeadAttention: B=4, S=2048, E=1024, H=16, D=64, fp32
// Projections: mma.sync bf16-split (3-MMA) GEMM (compute_103-safe PTX).
// Attention: fp32 register-blocked flash kernel (round-5 proven).
// ---------------------------------------------------------------------------

#define B_    4
#define S_    2048
#define E_    1024
#define H_    16
#define D_    64
#define M_    (B_ * S_)          // 8192

// ---- scratch (device globals; no allocation allowed) ----------------------
__device__ float g_Qt[M_ * E_];   // [(b*16+h)*64 + d][s]
__device__ float g_Kt[M_ * E_];
__device__ float g_V [M_ * E_];   // [b][s][h*64+d]
__device__ float g_O [M_ * E_];
__device__ __nv_bfloat16 g_Ahi[M_ * E_];
__device__ __nv_bfloat16 g_Alo[M_ * E_];
__device__ __nv_bfloat16 g_Whi[E_ * E_];   // transposed: [n][k]
__device__ __nv_bfloat16 g_Wlo[E_ * E_];

__device__ __forceinline__ uint32_t smem_u32(const void* p) {
    uint32_t a;
    asm("{ .reg .u64 t; cvta.to.shared.u64 t, %1; cvt.u32.u64 %0, t; }"
        : "=r"(a) : "l"(p));
    return a;
}

__device__ __forceinline__ void ldsm_x4(uint32_t& r0, uint32_t& r1,
                                        uint32_t& r2, uint32_t& r3, uint32_t addr) {
    asm volatile("ldmatrix.sync.aligned.m8n8.x4.shared.b16 {%0,%1,%2,%3}, [%4];"
                 : "=r"(r0), "=r"(r1), "=r"(r2), "=r"(r3) : "r"(addr));
}

__device__ __forceinline__ void mma16816(float* c, const uint32_t* a, const uint32_t* b) {
    asm volatile("mma.sync.aligned.m16n8k16.row.col.f32.bf16.bf16.f32 "
                 "{%0,%1,%2,%3}, {%4,%5,%6,%7}, {%8,%9}, {%0,%1,%2,%3};"
                 : "+f"(c[0]), "+f"(c[1]), "+f"(c[2]), "+f"(c[3])
                 : "r"(a[0]), "r"(a[1]), "r"(a[2]), "r"(a[3]), "r"(b[0]), "r"(b[1]));
}

// ---------------------------------------------------------------------------
// Conversion: fp32 activations -> bf16 hi/lo (elementwise, float4)
// ---------------------------------------------------------------------------
__global__ void __launch_bounds__(256) split_act_kernel(
    const float4* __restrict__ X, __nv_bfloat162* __restrict__ hi,
    __nv_bfloat162* __restrict__ lo)
{
    int i = blockIdx.x * 256 + threadIdx.x;     // over M_*E_/4
    float4 v = X[i];
    __nv_bfloat16 h0 = __float2bfloat16(v.x);
    __nv_bfloat16 h1 = __float2bfloat16(v.y);
    __nv_bfloat16 h2 = __float2bfloat16(v.z);
    __nv_bfloat16 h3 = __float2bfloat16(v.w);
    __nv_bfloat16 l0 = __float2bfloat16(v.x - __bfloat162float(h0));
    __nv_bfloat16 l1 = __float2bfloat16(v.y - __bfloat162float(h1));
    __nv_bfloat16 l2 = __float2bfloat16(v.z - __bfloat162float(h2));
    __nv_bfloat16 l3 = __float2bfloat16(v.w - __bfloat162float(h3));
    hi[2 * i]     = __nv_bfloat162{h0, h1};
    hi[2 * i + 1] = __nv_bfloat162{h2, h3};
    lo[2 * i]     = __nv_bfloat162{l0, l1};
    lo[2 * i + 1] = __nv_bfloat162{l2, l3};
}

// ---------------------------------------------------------------------------
// Conversion: W[K][N] fp32 -> Wt hi/lo bf16 [N][K] (transpose + split)
// ---------------------------------------------------------------------------
__global__ void __launch_bounds__(256) split_wT_kernel(
    const float* __restrict__ W, __nv_bfloat16* __restrict__ hi,
    __nv_bfloat16* __restrict__ lo)
{
    __shared__ float t[32][33];
    const int n0 = blockIdx.x * 32, k0 = blockIdx.y * 32;
    const int tx = threadIdx.x, ty = threadIdx.y;
    #pragma unroll
    for (int i = 0; i < 4; i++) {
        int kk = ty + i * 8;
        t[kk][tx] = W[(size_t)(k0 + kk) * E_ + n0 + tx];
    }
    __syncthreads();
    #pragma unroll
    for (int i = 0; i < 4; i++) {
        int nn = ty + i * 8;
        float v = t[tx][nn];
        __nv_bfloat16 h = __float2bfloat16(v);
        size_t idx = (size_t)(n0 + nn) * E_ + k0 + tx;
        hi[idx] = h;
        lo[idx] = __float2bfloat16(v - __bfloat162float(h));
    }
}

// ---------------------------------------------------------------------------
// mma.sync bf16-split GEMM: C[M,1024] = A[M,1024] @ W + bias
// A hi/lo bf16 [M][K]; W hi/lo bf16 [N][K].  Tile 128x128, 8 warps (64x32 each).
// K staged in 64-wide smem chunks, rows padded to 72 bf16 (144B).
// 3 terms per k16 step: AhiBhi + AhiBlo + AloBhi, fp32 accumulators.
// transposed=0: C[m][n].  transposed=1: Ct[(b*1024+n)*2048 + s].
// ---------------------------------------------------------------------------
#define PAD_   72                      // bf16 per padded row
#define TILEB_ (128 * PAD_ * 2)        // 18432 bytes per buffer
#define GT_SMEM_TOTAL (4 * TILEB_)     // 73728 bytes

__global__ void __launch_bounds__(256, 2) gemm_tc_kernel(
    const __nv_bfloat16* __restrict__ Ahi, const __nv_bfloat16* __restrict__ Alo,
    const __nv_bfloat16* __restrict__ Bhi, const __nv_bfloat16* __restrict__ Blo,
    const float* __restrict__ bias, float* __restrict__ C, int transposed)
{
    extern __shared__ __align__(16) char smem[];
    const uint32_t sb = smem_u32(smem);
    const uint32_t sAhi = sb;
    const uint32_t sAlo = sb + TILEB_;
    const uint32_t sBhi = sb + 2 * TILEB_;
    const uint32_t sBlo = sb + 3 * TILEB_;

    const int tid  = threadIdx.x;
    const int lane = tid & 31;
    const int wid  = tid >> 5;
    const int wm   = wid >> 2;        // 0..1 -> m offset wm*64
    const int wn   = wid & 3;         // 0..3 -> n offset wn*32
    const int m0   = blockIdx.y * 128;
    const int n0   = blockIdx.x * 128;

    const int i8  = lane & 7;
    const int sel = lane >> 3;

    // ldmatrix lane-address bases (byte offsets into a tile buffer)
    // A x4 (16x16): sel0: (r+i8, k+0) sel1: (r+8+i8, k+0) sel2: (r+i8, k+8) sel3: (r+8+i8, k+8)
    const uint32_t aBase = (uint32_t)((wm * 64 + i8 + ((sel & 1) << 3)) * (PAD_ * 2)
                                      + ((sel >> 1) << 3) * 2);
    // B x4 (two n8 tiles x k16): sel0: (n+i8, k) sel1: (n+i8, k+8) sel2: (n+8+i8, k) sel3: (n+8+i8, k+8)
    const uint32_t bBase = (uint32_t)((wn * 32 + i8 + ((sel >> 1) << 3)) * (PAD_ * 2)
                                      + ((sel & 1) << 3) * 2);

    float acc[4][4][4];                 // [mt][nt][4]
    #pragma unroll
    for (int mt = 0; mt < 4; mt++)
        #pragma unroll
        for (int nt = 0; nt < 4; nt++)
            #pragma unroll
            for (int e = 0; e < 4; e++) acc[mt][nt][e] = 0.f;

    // loader mapping: 1024 16B-chunks per buffer
    const int lr = tid >> 3;            // row 0..31 step -> r = lr + i*32
    const int lj = tid & 7;             // 16B chunk within 128B row

    for (int c = 0; c < 16; c++) {
        const int k0c = c * 64;

        __syncthreads();
        #pragma unroll
        for (int i = 0; i < 4; i++) {
            int r = lr + i * 32;
            uint32_t so = (uint32_t)(r * (PAD_ * 2) + lj * 16);
            size_t aoff = ((size_t)(m0 + r) * E_ + k0c) * 2 + lj * 16;
            size_t boff = ((size_t)(n0 + r) * E_ + k0c) * 2 + lj * 16;
            *(int4*)(smem + so)              = *(const int4*)((const char*)Ahi + aoff);
            *(int4*)(smem + TILEB_ + so)     = *(const int4*)((const char*)Alo + aoff);
            *(int4*)(smem + 2 * TILEB_ + so) = *(const int4*)((const char*)Bhi + boff);
            *(int4*)(smem + 3 * TILEB_ + so) = *(const int4*)((const char*)Blo + boff);
        }
        __syncthreads();

        #pragma unroll
        for (int ks = 0; ks < 4; ks++) {
            const uint32_t kOff = (uint32_t)(ks * 16 * 2);
            uint32_t a[4][4], bh[2][4], bl[2][4];

            #pragma unroll
            for (int mt = 0; mt < 4; mt++)
                ldsm_x4(a[mt][0], a[mt][1], a[mt][2], a[mt][3],
                        sAhi + aBase + (uint32_t)(mt * 16 * PAD_ * 2) + kOff);
            #pragma unroll
            for (int p = 0; p < 2; p++) {
                ldsm_x4(bh[p][0], bh[p][1], bh[p][2], bh[p][3],
                        sBhi + bBase + (uint32_t)(p * 16 * PAD_ * 2) + kOff);
                ldsm_x4(bl[p][0], bl[p][1], bl[p][2], bl[p][3],
                        sBlo + bBase + (uint32_t)(p * 16 * PAD_ * 2) + kOff);
            }

            // Ahi * Bhi  and  Ahi * Blo
            #pragma unroll
            for (int mt = 0; mt < 4; mt++)
                #pragma unroll
                for (int nt = 0; nt < 4; nt++) {
                    mma16816(acc[mt][nt], a[mt], &bh[nt >> 1][(nt & 1) * 2]);
                    mma16816(acc[mt][nt], a[mt], &bl[nt >> 1][(nt & 1) * 2]);
                }

            // Alo * Bhi
            #pragma unroll
            for (int mt = 0; mt < 4; mt++)
                ldsm_x4(a[mt][0], a[mt][1], a[mt][2], a[mt][3],
                        sAlo + aBase + (uint32_t)(mt * 16 * PAD_ * 2) + kOff);
            #pragma unroll
            for (int mt = 0; mt < 4; mt++)
                #pragma unroll
                for (int nt = 0; nt < 4; nt++)
                    mma16816(acc[mt][nt], a[mt], &bh[nt >> 1][(nt & 1) * 2]);
        }
    }

    // epilogue: thread holds C[row = 16mt + g (+8)][col = 8nt + 2tig + {0,1}]
    const int g   = lane >> 2;
    const int tig = lane & 3;
    if (!transposed) {
        #pragma unroll
        for (int mt = 0; mt < 4; mt++) {
            #pragma unroll
            for (int half = 0; half < 2; half++) {
                int row = m0 + wm * 64 + mt * 16 + g + half * 8;
                float* dst = C + ((size_t)row << 10) + n0 + wn * 32;
                #pragma unroll
                for (int nt = 0; nt < 4; nt++) {
                    int col = nt * 8 + tig * 2;
                    float2 o;
                    o.x = acc[mt][nt][half * 2 + 0] + bias[n0 + wn * 32 + col];
                    o.y = acc[mt][nt][half * 2 + 1] + bias[n0 + wn * 32 + col + 1];
                    *(float2*)(dst + col) = o;
                }
            }
        }
    } else {
        const int b    = m0 >> 11;
        const int sbase = (m0 & 2047) + wm * 64;
        #pragma unroll
        for (int mt = 0; mt < 4; mt++) {
            #pragma unroll
            for (int half = 0; half < 2; half++) {
                int sloc = sbase + mt * 16 + g + half * 8;
                #pragma unroll
                for (int nt = 0; nt < 4; nt++) {
                    int nn = n0 + wn * 32 + nt * 8 + tig * 2;
                    float bn0 = bias[nn], bn1 = bias[nn + 1];
                    C[(((size_t)(b << 10) + nn) << 11) + sloc] =
                        acc[mt][nt][half * 2 + 0] + bn0;
                    C[(((size_t)(b << 10) + nn + 1) << 11) + sloc] =
                        acc[mt][nt][half * 2 + 1] + bn1;
                }
            }
        }
    }
}

// ---------------------------------------------------------------------------
// Flash-style attention (round-5, unchanged): fp32, register-blocked.
// ---------------------------------------------------------------------------
__global__ void __launch_bounds__(256, 2) attn_kernel(
    const float* __restrict__ Qt,   // [(bh)*64 + d][s]
    const float* __restrict__ Kt,   // [(bh)*64 + d][s]
    const float* __restrict__ V,    // [b][s][h*64 + d]
    float* __restrict__ O)          // [b][s][h*64 + d]
{
    extern __shared__ __align__(16) float sm[];
    float* Qs  = sm;             // [64][128]  d-major, pre-scaled by 1/8
    float* KPs = sm + 8192;      // K: [64][64] d-major ; later P: [128][64]
    float* Vs  = sm + 16384;     // [64][64]   j-major

    const int tid = threadIdx.x;
    const int tx  = tid & 15;
    const int ty  = tid >> 4;
    const int q0  = blockIdx.x * 128;
    const int bh  = blockIdx.y;
    const int b   = bh >> 4;
    const int h   = bh & 15;

    const size_t qtBase = (size_t)bh * 64 * S_;

    #pragma unroll
    for (int i = 0; i < 8; i++) {
        int linear = tid + i * 256;
        int qf = linear & 31;
        int d  = linear >> 5;
        float4 v = *(const float4*)&Qt[qtBase + (size_t)d * S_ + q0 + qf * 4];
        v.x *= 0.125f; v.y *= 0.125f; v.z *= 0.125f; v.w *= 0.125f;
        ((float4*)Qs)[d * 32 + qf] = v;
    }

    float m_run[8], l_run[8], acc[8][4];
    #pragma unroll
    for (int r = 0; r < 8; r++) {
        m_run[r] = -1e30f; l_run[r] = 0.f;
        acc[r][0] = acc[r][1] = acc[r][2] = acc[r][3] = 0.f;
    }

    for (int t = 0; t < S_ / 64; t++) {
        const int j0 = t * 64;

        __syncthreads();
        #pragma unroll
        for (int i = 0; i < 4; i++) {
            int linear = tid + i * 256;
            int f = linear & 15;
            int r = linear >> 4;
            ((float4*)KPs)[r * 16 + f] =
                *(const float4*)&Kt[qtBase + (size_t)r * S_ + j0 + f * 4];
            ((float4*)Vs)[r * 16 + f] =
                *(const float4*)&V[((size_t)(b * S_ + j0 + r) << 10) + h * 64 + f * 4];
        }
        __syncthreads();

        float s[8][4];
        #pragma unroll
        for (int r = 0; r < 8; r++) s[r][0] = s[r][1] = s[r][2] = s[r][3] = 0.f;

        {
            const float4* Q4 = (const float4*)Qs + ty * 2;
            const float4* K4 = (const float4*)KPs + tx;
            #pragma unroll 4
            for (int kk = 0; kk < 64; kk++) {
                float4 qa = Q4[kk * 32];
                float4 qb = Q4[kk * 32 + 1];
                float4 kv = K4[kk * 16];
                float qr[8] = {qa.x, qa.y, qa.z, qa.w, qb.x, qb.y, qb.z, qb.w};
                #pragma unroll
                for (int r = 0; r < 8; r++) {
                    s[r][0] += qr[r] * kv.x;
                    s[r][1] += qr[r] * kv.y;
                    s[r][2] += qr[r] * kv.z;
                    s[r][3] += qr[r] * kv.w;
                }
            }
        }

        #pragma unroll
        for (int r = 0; r < 8; r++) {
            float mt = fmaxf(fmaxf(s[r][0], s[r][1]), fmaxf(s[r][2], s[r][3]));
            mt = fmaxf(mt, __shfl_xor_sync(0xffffffffu, mt, 1));
            mt = fmaxf(mt, __shfl_xor_sync(0xffffffffu, mt, 2));
            mt = fmaxf(mt, __shfl_xor_sync(0xffffffffu, mt, 4));
            mt = fmaxf(mt, __shfl_xor_sync(0xffffffffu, mt, 8));
            float m_new = fmaxf(m_run[r], mt);
            float corr  = __expf(m_run[r] - m_new);
            m_run[r] = m_new;
            float lt = 0.f;
            #pragma unroll
            for (int cc = 0; cc < 4; cc++) {
                s[r][cc] = __expf(s[r][cc] - m_new);
                lt += s[r][cc];
            }
            lt += __shfl_xor_sync(0xffffffffu, lt, 1);
            lt += __shfl_xor_sync(0xffffffffu, lt, 2);
            lt += __shfl_xor_sync(0xffffffffu, lt, 4);
            lt += __shfl_xor_sync(0xffffffffu, lt, 8);
            l_run[r] = l_run[r] * corr + lt;
            acc[r][0] *= corr; acc[r][1] *= corr;
            acc[r][2] *= corr; acc[r][3] *= corr;
        }

        __syncthreads();
        #pragma unroll
        for (int r = 0; r < 8; r++)
            ((float4*)KPs)[(ty * 8 + r) * 16 + tx] =
                make_float4(s[r][0], s[r][1], s[r][2], s[r][3]);
        __syncthreads();

        {
            const float4* V4 = (const float4*)Vs + tx;
            const float*  P  = KPs + ty * 8 * 64;
            #pragma unroll 2
            for (int j = 0; j < 64; j++) {
                float4 vv = V4[j * 16];
                #pragma unroll
                for (int r = 0; r < 8; r++) {
                    float p = P[r * 64 + j];
                    acc[r][0] += p * vv.x;
                    acc[r][1] += p * vv.y;
                    acc[r][2] += p * vv.z;
                    acc[r][3] += p * vv.w;
                }
            }
        }
    }

    #pragma unroll
    for (int r = 0; r < 8; r++) {
        float inv = 1.f / l_run[r];
        float4 o;
        o.x = acc[r][0] * inv;
        o.y = acc[r][1] * inv;
        o.z = acc[r][2] * inv;
        o.w = acc[r][3] * inv;
        *(float4*)&O[((size_t)(b * S_ + q0 + ty * 8 + r) << 10) + h * 64 + tx * 4] = o;
    }
}

// ---------------------------------------------------------------------------
extern "C" void kernel_launch(void* const* d_in, const int* in_sizes, int n_in,
                              void* d_out, int out_size)
{
    const float* value = (const float*)d_in[0];
    const float* key_  = (const float*)d_in[1];
    const float* query = (const float*)d_in[2];
    const float* Wv = (const float*)d_in[3];
    const float* bv = (const float*)d_in[4];
    const float* Wk = (const float*)d_in[5];
    const float* bk = (const float*)d_in[6];
    const float* Wq = (const float*)d_in[7];
    const float* bq = (const float*)d_in[8];
    const float* Wo = (const float*)d_in[9];
    const float* bo = (const float*)d_in[10];
    float* out = (float*)d_out;

    float *gqt, *gkt, *gv, *go;
    __nv_bfloat16 *ahi, *alo, *whi, *wlo;
    cudaGetSymbolAddress((void**)&gqt, g_Qt);
    cudaGetSymbolAddress((void**)&gkt, g_Kt);
    cudaGetSymbolAddress((void**)&gv,  g_V);
    cudaGetSymbolAddress((void**)&go,  g_O);
    cudaGetSymbolAddress((void**)&ahi, g_Ahi);
    cudaGetSymbolAddress((void**)&alo, g_Alo);
    cudaGetSymbolAddress((void**)&whi, g_Whi);
    cudaGetSymbolAddress((void**)&wlo, g_Wlo);

    static int attr_set = 0;
    if (!attr_set) {
        cudaFuncSetAttribute(attn_kernel,
                             cudaFuncAttributeMaxDynamicSharedMemorySize,
                             20480 * sizeof(float));
        cudaFuncSetAttribute(gemm_tc_kernel,
                             cudaFuncAttributeMaxDynamicSharedMemorySize,
                             GT_SMEM_TOTAL);
        attr_set = 1;
    }

    const dim3 cw_grid(32, 32), cw_blk(32, 8);
    const int ca_grid = (M_ * E_ / 4) / 256;           // 8192 blocks
    const dim3 g_grid(E_ / 128, M_ / 128);             // (8, 64)

    // V projection (normal layout)
    split_wT_kernel<<<cw_grid, cw_blk>>>(Wv, whi, wlo);
    split_act_kernel<<<ca_grid, 256>>>((const float4*)value,
                                       (__nv_bfloat162*)ahi, (__nv_bfloat162*)alo);
    gemm_tc_kernel<<<g_grid, 256, GT_SMEM_TOTAL>>>(ahi, alo, whi, wlo, bv, gv, 0);

    // K projection (transposed layout)
    split_wT_kernel<<<cw_grid, cw_blk>>>(Wk, whi, wlo);
    split_act_kernel<<<ca_grid, 256>>>((const float4*)key_,
                                       (__nv_bfloat162*)ahi, (__nv_bfloat162*)alo);
    gemm_tc_kernel<<<g_grid, 256, GT_SMEM_TOTAL>>>(ahi, alo, whi, wlo, bk, gkt, 1);

    // Q projection (transposed layout)
    split_wT_kernel<<<cw_grid, cw_blk>>>(Wq, whi, wlo);
    split_act_kernel<<<ca_grid, 256>>>((const float4*)query,
                                       (__nv_bfloat162*)ahi, (__nv_bfloat162*)alo);
    gemm_tc_kernel<<<g_grid, 256, GT_SMEM_TOTAL>>>(ahi, alo, whi, wlo, bq, gqt, 1);

    // attention
    attn_kernel<<<dim3(S_ / 128, B_ * H_), 256, 20480 * sizeof(float)>>>(gqt, gkt, gv, go);

    // output projection
    split_wT_kernel<<<cw_grid, cw_blk>>>(Wo, whi, wlo);
    split_act_kernel<<<ca_grid, 256>>>((const float4*)go,
                                       (__nv_bfloat162*)ahi, (__nv_bfloat162*)alo);
    gemm_tc_kernel<<<g_grid, 256, GT_SMEM_TOTAL>>>(ahi, alo, whi, wlo, bo, out, 0);
}

// round 9
// speedup vs baseline: 10.9835x; 2.6148x over previous
#include <cuda_runtime.h>
#include <cuda_bf16.h>
#include <cuda_fp16.h>
#include <cstdint>

// ---------------------------------------------------------------------------
// MultiHeadAttention: B=4, S=2048, E=1024, H=16, D=64, fp32
// Projections: mma.sync bf16-split GEMM. Attention: fp16 mma.sync flash.
// ---------------------------------------------------------------------------

#define B_    4
#define S_    2048
#define E_    1024
#define H_    16
#define D_    64
#define M_    (B_ * S_)          // 8192

// ---- scratch (device globals; no allocation allowed) ----------------------
__device__ float  g_O [M_ * E_];            // attention output (fp32)
__device__ __half g_Qh[M_ * E_];            // [b][s][h*64+d], pre-scaled by 1/8
__device__ __half g_Kh[M_ * E_];            // [b][s][h*64+d]
__device__ __half g_Vt[M_ * E_];            // [(b*16+h)*64+d][s]
__device__ __nv_bfloat16 g_Ahi[M_ * E_];
__device__ __nv_bfloat16 g_Alo[M_ * E_];
__device__ __nv_bfloat16 g_Whi[E_ * E_];    // transposed: [n][k]
__device__ __nv_bfloat16 g_Wlo[E_ * E_];

__device__ __forceinline__ uint32_t smem_u32(const void* p) {
    uint32_t a;
    asm("{ .reg .u64 t; cvta.to.shared.u64 t, %1; cvt.u32.u64 %0, t; }"
        : "=r"(a) : "l"(p));
    return a;
}
__device__ __forceinline__ void ldsm_x4(uint32_t* r, uint32_t addr) {
    asm volatile("ldmatrix.sync.aligned.m8n8.x4.shared.b16 {%0,%1,%2,%3}, [%4];"
                 : "=r"(r[0]), "=r"(r[1]), "=r"(r[2]), "=r"(r[3]) : "r"(addr));
}
__device__ __forceinline__ void mma_bf(float* c, const uint32_t* a, const uint32_t* b) {
    asm volatile("mma.sync.aligned.m16n8k16.row.col.f32.bf16.bf16.f32 "
                 "{%0,%1,%2,%3}, {%4,%5,%6,%7}, {%8,%9}, {%0,%1,%2,%3};"
                 : "+f"(c[0]), "+f"(c[1]), "+f"(c[2]), "+f"(c[3])
                 : "r"(a[0]), "r"(a[1]), "r"(a[2]), "r"(a[3]), "r"(b[0]), "r"(b[1]));
}
__device__ __forceinline__ void mma_fp16(float* c, const uint32_t* a, const uint32_t* b) {
    asm volatile("mma.sync.aligned.m16n8k16.row.col.f32.f16.f16.f32 "
                 "{%0,%1,%2,%3}, {%4,%5,%6,%7}, {%8,%9}, {%0,%1,%2,%3};"
                 : "+f"(c[0]), "+f"(c[1]), "+f"(c[2]), "+f"(c[3])
                 : "r"(a[0]), "r"(a[1]), "r"(a[2]), "r"(a[3]), "r"(b[0]), "r"(b[1]));
}
#define CP_ASYNC16(s, g) \
    asm volatile("cp.async.cg.shared.global [%0], [%1], 16;" :: "r"(s), "l"(g))
#define CP_COMMIT() asm volatile("cp.async.commit_group;")
#define CP_WAIT0()  asm volatile("cp.async.wait_group 0;")

__device__ __forceinline__ uint32_t packh2(float a, float b) {
    __half2 h = __floats2half2_rn(a, b);
    return *(uint32_t*)&h;
}

// ---------------------------------------------------------------------------
// fp32 -> bf16 hi/lo splits
// ---------------------------------------------------------------------------
__global__ void __launch_bounds__(256) split_act_kernel(
    const float4* __restrict__ X, __nv_bfloat162* __restrict__ hi,
    __nv_bfloat162* __restrict__ lo)
{
    int i = blockIdx.x * 256 + threadIdx.x;
    float4 v = X[i];
    __nv_bfloat16 h0 = __float2bfloat16(v.x);
    __nv_bfloat16 h1 = __float2bfloat16(v.y);
    __nv_bfloat16 h2 = __float2bfloat16(v.z);
    __nv_bfloat16 h3 = __float2bfloat16(v.w);
    __nv_bfloat16 l0 = __float2bfloat16(v.x - __bfloat162float(h0));
    __nv_bfloat16 l1 = __float2bfloat16(v.y - __bfloat162float(h1));
    __nv_bfloat16 l2 = __float2bfloat16(v.z - __bfloat162float(h2));
    __nv_bfloat16 l3 = __float2bfloat16(v.w - __bfloat162float(h3));
    hi[2 * i]     = __nv_bfloat162{h0, h1};
    hi[2 * i + 1] = __nv_bfloat162{h2, h3};
    lo[2 * i]     = __nv_bfloat162{l0, l1};
    lo[2 * i + 1] = __nv_bfloat162{l2, l3};
}

__global__ void __launch_bounds__(256) split_wT_kernel(
    const float* __restrict__ W, __nv_bfloat16* __restrict__ hi,
    __nv_bfloat16* __restrict__ lo)
{
    __shared__ float t[32][33];
    const int n0 = blockIdx.x * 32, k0 = blockIdx.y * 32;
    const int tx = threadIdx.x, ty = threadIdx.y;
    #pragma unroll
    for (int i = 0; i < 4; i++) {
        int kk = ty + i * 8;
        t[kk][tx] = W[(size_t)(k0 + kk) * E_ + n0 + tx];
    }
    __syncthreads();
    #pragma unroll
    for (int i = 0; i < 4; i++) {
        int nn = ty + i * 8;
        float v = t[tx][nn];
        __nv_bfloat16 h = __float2bfloat16(v);
        size_t idx = (size_t)(n0 + nn) * E_ + k0 + tx;
        hi[idx] = h;
        lo[idx] = __float2bfloat16(v - __bfloat162float(h));
    }
}

// ---------------------------------------------------------------------------
// mma.sync bf16-split GEMM, tile 128x128, 8 warps (64x32 each).
// mode 0: fp32 C[m][n].  mode 1: fp16 C[m][n] (scaled).  mode 2: fp16
// transposed Ct[(b*1024+n)*2048+s] (scaled).
// ---------------------------------------------------------------------------
#define PAD_   72
#define TILEB_ (128 * PAD_ * 2)
#define GT_SMEM_TOTAL (4 * TILEB_)

__global__ void __launch_bounds__(256, 2) gemm_tc_kernel(
    const __nv_bfloat16* __restrict__ Ahi, const __nv_bfloat16* __restrict__ Alo,
    const __nv_bfloat16* __restrict__ Bhi, const __nv_bfloat16* __restrict__ Blo,
    const float* __restrict__ bias, void* __restrict__ C, int mode, float scale)
{
    extern __shared__ __align__(16) char smem[];
    const uint32_t sb = smem_u32(smem);
    const uint32_t sAhi = sb;
    const uint32_t sAlo = sb + TILEB_;
    const uint32_t sBhi = sb + 2 * TILEB_;
    const uint32_t sBlo = sb + 3 * TILEB_;

    const int tid  = threadIdx.x;
    const int lane = tid & 31;
    const int wid  = tid >> 5;
    const int wm   = wid >> 2;
    const int wn   = wid & 3;
    const int m0   = blockIdx.y * 128;
    const int n0   = blockIdx.x * 128;

    const int i8  = lane & 7;
    const int sel = lane >> 3;

    const uint32_t aBase = (uint32_t)((wm * 64 + i8 + ((sel & 1) << 3)) * (PAD_ * 2)
                                      + ((sel >> 1) << 3) * 2);
    const uint32_t bBase = (uint32_t)((wn * 32 + i8 + ((sel >> 1) << 3)) * (PAD_ * 2)
                                      + ((sel & 1) << 3) * 2);

    float acc[4][4][4];
    #pragma unroll
    for (int mt = 0; mt < 4; mt++)
        #pragma unroll
        for (int nt = 0; nt < 4; nt++)
            #pragma unroll
            for (int e = 0; e < 4; e++) acc[mt][nt][e] = 0.f;

    const int lr = tid >> 3;
    const int lj = tid & 7;

    for (int c = 0; c < 16; c++) {
        const int k0c = c * 64;

        __syncthreads();
        #pragma unroll
        for (int i = 0; i < 4; i++) {
            int r = lr + i * 32;
            uint32_t so = (uint32_t)(r * (PAD_ * 2) + lj * 16);
            size_t aoff = ((size_t)(m0 + r) * E_ + k0c) * 2 + lj * 16;
            size_t boff = ((size_t)(n0 + r) * E_ + k0c) * 2 + lj * 16;
            *(int4*)(smem + so)              = *(const int4*)((const char*)Ahi + aoff);
            *(int4*)(smem + TILEB_ + so)     = *(const int4*)((const char*)Alo + aoff);
            *(int4*)(smem + 2 * TILEB_ + so) = *(const int4*)((const char*)Bhi + boff);
            *(int4*)(smem + 3 * TILEB_ + so) = *(const int4*)((const char*)Blo + boff);
        }
        __syncthreads();

        #pragma unroll
        for (int ks = 0; ks < 4; ks++) {
            const uint32_t kOff = (uint32_t)(ks * 16 * 2);
            uint32_t a[4][4], bh[2][4], bl[2][4];

            #pragma unroll
            for (int mt = 0; mt < 4; mt++)
                ldsm_x4(a[mt], sAhi + aBase + (uint32_t)(mt * 16 * PAD_ * 2) + kOff);
            #pragma unroll
            for (int p = 0; p < 2; p++) {
                ldsm_x4(bh[p], sBhi + bBase + (uint32_t)(p * 16 * PAD_ * 2) + kOff);
                ldsm_x4(bl[p], sBlo + bBase + (uint32_t)(p * 16 * PAD_ * 2) + kOff);
            }

            #pragma unroll
            for (int mt = 0; mt < 4; mt++)
                #pragma unroll
                for (int nt = 0; nt < 4; nt++) {
                    mma_bf(acc[mt][nt], a[mt], &bh[nt >> 1][(nt & 1) * 2]);
                    mma_bf(acc[mt][nt], a[mt], &bl[nt >> 1][(nt & 1) * 2]);
                }

            #pragma unroll
            for (int mt = 0; mt < 4; mt++)
                ldsm_x4(a[mt], sAlo + aBase + (uint32_t)(mt * 16 * PAD_ * 2) + kOff);
            #pragma unroll
            for (int mt = 0; mt < 4; mt++)
                #pragma unroll
                for (int nt = 0; nt < 4; nt++)
                    mma_bf(acc[mt][nt], a[mt], &bh[nt >> 1][(nt & 1) * 2]);
        }
    }

    const int g   = lane >> 2;
    const int tig = lane & 3;
    if (mode == 0) {
        float* Cf = (float*)C;
        #pragma unroll
        for (int mt = 0; mt < 4; mt++)
            #pragma unroll
            for (int half = 0; half < 2; half++) {
                int row = m0 + wm * 64 + mt * 16 + g + half * 8;
                float* dst = Cf + ((size_t)row << 10) + n0 + wn * 32;
                #pragma unroll
                for (int nt = 0; nt < 4; nt++) {
                    int col = nt * 8 + tig * 2;
                    float2 o;
                    o.x = acc[mt][nt][half * 2 + 0] + bias[n0 + wn * 32 + col];
                    o.y = acc[mt][nt][half * 2 + 1] + bias[n0 + wn * 32 + col + 1];
                    *(float2*)(dst + col) = o;
                }
            }
    } else if (mode == 1) {
        __half* Ch = (__half*)C;
        #pragma unroll
        for (int mt = 0; mt < 4; mt++)
            #pragma unroll
            for (int half = 0; half < 2; half++) {
                int row = m0 + wm * 64 + mt * 16 + g + half * 8;
                __half* dst = Ch + ((size_t)row << 10) + n0 + wn * 32;
                #pragma unroll
                for (int nt = 0; nt < 4; nt++) {
                    int col = nt * 8 + tig * 2;
                    float vx = (acc[mt][nt][half * 2 + 0] + bias[n0 + wn * 32 + col]) * scale;
                    float vy = (acc[mt][nt][half * 2 + 1] + bias[n0 + wn * 32 + col + 1]) * scale;
                    *(__half2*)(dst + col) = __floats2half2_rn(vx, vy);
                }
            }
    } else {
        __half* Ch = (__half*)C;
        const int b     = m0 >> 11;
        const int sbase = (m0 & 2047) + wm * 64;
        #pragma unroll
        for (int mt = 0; mt < 4; mt++)
            #pragma unroll
            for (int half = 0; half < 2; half++) {
                int sloc = sbase + mt * 16 + g + half * 8;
                #pragma unroll
                for (int nt = 0; nt < 4; nt++) {
                    int nn = n0 + wn * 32 + nt * 8 + tig * 2;
                    float v0 = (acc[mt][nt][half * 2 + 0] + bias[nn]) * scale;
                    float v1 = (acc[mt][nt][half * 2 + 1] + bias[nn + 1]) * scale;
                    Ch[(((size_t)(b << 10) + nn) << 11) + sloc]     = __float2half(v0);
                    Ch[(((size_t)(b << 10) + nn + 1) << 11) + sloc] = __float2half(v1);
                }
            }
    }
}

// ---------------------------------------------------------------------------
// fp16 mma.sync flash attention.
// CTA: 128 q rows of one (b,h); 8 warps, warp w owns q rows [16w,16w+16).
// KV tiles of 64; K/V double-buffered via cp.async; P stays in registers.
// Smem rows padded to 144B (ldmatrix conflict-free, as in GEMM).
// ---------------------------------------------------------------------------
#define AT_ROWB 144
#define AT_Q    (128 * AT_ROWB)            // 18432
#define AT_KV   (64 * AT_ROWB)             // 9216
#define AT_SMEM (AT_Q + 4 * AT_KV)         // 55296

__global__ void __launch_bounds__(256, 2) attn_tc_kernel(
    const __half* __restrict__ Qh,   // [b][s][h*64+d], pre-scaled 1/8
    const __half* __restrict__ Kh,   // [b][s][h*64+d]
    const __half* __restrict__ Vt,   // [(bh)*64+d][s]
    float* __restrict__ O)           // [b][s][h*64+d]
{
    extern __shared__ __align__(16) char sm[];
    const uint32_t sb = smem_u32(sm);
    const uint32_t sQ = sb;
    const uint32_t sK0 = sb + AT_Q;
    const uint32_t sV0 = sb + AT_Q + 2 * AT_KV;

    const int tid  = threadIdx.x;
    const int lane = tid & 31;
    const int wid  = tid >> 5;
    const int q0   = blockIdx.x * 128;
    const int bh   = blockIdx.y;
    const int b    = bh >> 4;
    const int h    = bh & 15;

    const int lr = tid >> 3;          // 0..31
    const int lc = tid & 7;           // 16B chunk

    const __half* Qg = Qh + ((size_t)(b * S_ + q0) << 10) + h * 64;
    const __half* Kg = Kh + ((size_t)(b * S_) << 10) + h * 64;
    const __half* Vg = Vt + ((size_t)(bh * 64) << 11);

    // ---- issue Q (128 rows) + tile 0 ----
    #pragma unroll
    for (int i = 0; i < 4; i++) {
        int r = lr + i * 32;
        CP_ASYNC16(sQ + r * AT_ROWB + lc * 16, Qg + ((size_t)r << 10) + lc * 8);
    }
    #pragma unroll
    for (int i = 0; i < 2; i++) {
        int r = lr + i * 32;
        CP_ASYNC16(sK0 + r * AT_ROWB + lc * 16, Kg + ((size_t)r << 10) + lc * 8);
        CP_ASYNC16(sV0 + r * AT_ROWB + lc * 16, Vg + ((size_t)r << 11) + lc * 8);
    }
    CP_COMMIT();
    CP_WAIT0();
    __syncthreads();

    // ---- Q fragments (A, m16k16 x4 k-steps) ----
    const int i8  = lane & 7;
    const int sel = lane >> 3;
    const uint32_t aBase = sQ + (uint32_t)((wid * 16 + i8 + ((sel & 1) << 3)) * AT_ROWB
                                           + ((sel >> 1) << 3) * 2);
    const uint32_t bBase = (uint32_t)((i8 + ((sel >> 1) << 3)) * AT_ROWB
                                      + ((sel & 1) << 3) * 2);
    uint32_t qf[4][4];
    #pragma unroll
    for (int ks = 0; ks < 4; ks++) ldsm_x4(qf[ks], aBase + ks * 32);

    float m_run[2] = {-1e30f, -1e30f};
    float l_run[2] = {0.f, 0.f};
    float o[8][4];
    #pragma unroll
    for (int j = 0; j < 8; j++)
        o[j][0] = o[j][1] = o[j][2] = o[j][3] = 0.f;

    for (int t = 0; t < S_ / 64; t++) {
        const int buf = t & 1;
        const uint32_t sKt = sK0 + buf * AT_KV;
        const uint32_t sVt = sV0 + buf * AT_KV;

        // prefetch tile t+1 into the other buffer
        if (t + 1 < S_ / 64) {
            const int nb = (t + 1) & 1;
            const int j0 = (t + 1) * 64;
            #pragma unroll
            for (int i = 0; i < 2; i++) {
                int r = lr + i * 32;
                CP_ASYNC16(sK0 + nb * AT_KV + r * AT_ROWB + lc * 16,
                           Kg + ((size_t)(j0 + r) << 10) + lc * 8);
                CP_ASYNC16(sV0 + nb * AT_KV + r * AT_ROWB + lc * 16,
                           Vg + ((size_t)r << 11) + j0 + lc * 8);
            }
            CP_COMMIT();
        }

        // ---- S = Q K^T ----
        float s[8][4];
        #pragma unroll
        for (int j = 0; j < 8; j++)
            s[j][0] = s[j][1] = s[j][2] = s[j][3] = 0.f;

        #pragma unroll
        for (int ks = 0; ks < 4; ks++) {
            uint32_t kf[4][4];
            #pragma unroll
            for (int nt = 0; nt < 4; nt++)
                ldsm_x4(kf[nt], sKt + bBase + (uint32_t)(nt * 16 * AT_ROWB) + ks * 32);
            #pragma unroll
            for (int nt = 0; nt < 4; nt++) {
                mma_fp16(s[2 * nt],     qf[ks], &kf[nt][0]);
                mma_fp16(s[2 * nt + 1], qf[ks], &kf[nt][2]);
            }
        }

        // ---- online softmax (rows g and g+8; 4 lanes/row via shfl 1,2) ----
        #pragma unroll
        for (int half = 0; half < 2; half++) {
            const int c = half * 2;
            float mt = -1e30f;
            #pragma unroll
            for (int j = 0; j < 8; j++)
                mt = fmaxf(mt, fmaxf(s[j][c], s[j][c + 1]));
            mt = fmaxf(mt, __shfl_xor_sync(0xffffffffu, mt, 1));
            mt = fmaxf(mt, __shfl_xor_sync(0xffffffffu, mt, 2));
            float m_new = fmaxf(m_run[half], mt);
            float corr  = __expf(m_run[half] - m_new);
            m_run[half] = m_new;
            float lt = 0.f;
            #pragma unroll
            for (int j = 0; j < 8; j++) {
                s[j][c]     = __expf(s[j][c]     - m_new);
                s[j][c + 1] = __expf(s[j][c + 1] - m_new);
                lt += s[j][c] + s[j][c + 1];
            }
            lt += __shfl_xor_sync(0xffffffffu, lt, 1);
            lt += __shfl_xor_sync(0xffffffffu, lt, 2);
            l_run[half] = l_run[half] * corr + lt;
            #pragma unroll
            for (int j = 0; j < 8; j++) {
                o[j][c] *= corr;
                o[j][c + 1] *= corr;
            }
        }

        // ---- P fragments (registers) ----
        uint32_t pf[4][4];
        #pragma unroll
        for (int ks = 0; ks < 4; ks++) {
            pf[ks][0] = packh2(s[2 * ks][0],     s[2 * ks][1]);
            pf[ks][1] = packh2(s[2 * ks][2],     s[2 * ks][3]);
            pf[ks][2] = packh2(s[2 * ks + 1][0], s[2 * ks + 1][1]);
            pf[ks][3] = packh2(s[2 * ks + 1][2], s[2 * ks + 1][3]);
        }

        // ---- O += P V ----
        #pragma unroll
        for (int ks = 0; ks < 4; ks++) {
            uint32_t vf[4][4];
            #pragma unroll
            for (int nt = 0; nt < 4; nt++)
                ldsm_x4(vf[nt], sVt + bBase + (uint32_t)(nt * 16 * AT_ROWB) + ks * 32);
            #pragma unroll
            for (int nt = 0; nt < 4; nt++) {
                mma_fp16(o[2 * nt],     pf[ks], &vf[nt][0]);
                mma_fp16(o[2 * nt + 1], pf[ks], &vf[nt][2]);
            }
        }

        CP_WAIT0();
        __syncthreads();
    }

    // ---- normalize + write fp32 O ----
    const int g   = lane >> 2;
    const int tig = lane & 3;
    #pragma unroll
    for (int half = 0; half < 2; half++) {
        float inv = 1.f / l_run[half];
        int row = q0 + wid * 16 + g + half * 8;
        float* dst = O + ((size_t)(b * S_ + row) << 10) + h * 64;
        #pragma unroll
        for (int j = 0; j < 8; j++) {
            float2 v;
            v.x = o[j][half * 2 + 0] * inv;
            v.y = o[j][half * 2 + 1] * inv;
            *(float2*)(dst + j * 8 + tig * 2) = v;
        }
    }
}

// ---------------------------------------------------------------------------
extern "C" void kernel_launch(void* const* d_in, const int* in_sizes, int n_in,
                              void* d_out, int out_size)
{
    const float* value = (const float*)d_in[0];
    const float* key_  = (const float*)d_in[1];
    const float* query = (const float*)d_in[2];
    const float* Wv = (const float*)d_in[3];
    const float* bv = (const float*)d_in[4];
    const float* Wk = (const float*)d_in[5];
    const float* bk = (const float*)d_in[6];
    const float* Wq = (const float*)d_in[7];
    const float* bq = (const float*)d_in[8];
    const float* Wo = (const float*)d_in[9];
    const float* bo = (const float*)d_in[10];
    float* out = (float*)d_out;

    float* go;
    __half *qh, *kh, *vt;
    __nv_bfloat16 *ahi, *alo, *whi, *wlo;
    cudaGetSymbolAddress((void**)&go,  g_O);
    cudaGetSymbolAddress((void**)&qh,  g_Qh);
    cudaGetSymbolAddress((void**)&kh,  g_Kh);
    cudaGetSymbolAddress((void**)&vt,  g_Vt);
    cudaGetSymbolAddress((void**)&ahi, g_Ahi);
    cudaGetSymbolAddress((void**)&alo, g_Alo);
    cudaGetSymbolAddress((void**)&whi, g_Whi);
    cudaGetSymbolAddress((void**)&wlo, g_Wlo);

    static int attr_set = 0;
    if (!attr_set) {
        cudaFuncSetAttribute(gemm_tc_kernel,
                             cudaFuncAttributeMaxDynamicSharedMemorySize, GT_SMEM_TOTAL);
        cudaFuncSetAttribute(attn_tc_kernel,
                             cudaFuncAttributeMaxDynamicSharedMemorySize, AT_SMEM);
        attr_set = 1;
    }

    const dim3 cw_grid(32, 32), cw_blk(32, 8);
    const int ca_grid = (M_ * E_ / 4) / 256;
    const dim3 g_grid(E_ / 128, M_ / 128);

    // V projection -> fp16 transposed [bh*64+d][s]
    split_wT_kernel<<<cw_grid, cw_blk>>>(Wv, whi, wlo);
    split_act_kernel<<<ca_grid, 256>>>((const float4*)value,
                                       (__nv_bfloat162*)ahi, (__nv_bfloat162*)alo);
    gemm_tc_kernel<<<g_grid, 256, GT_SMEM_TOTAL>>>(ahi, alo, whi, wlo, bv, vt, 2, 1.0f);

    // K projection -> fp16 [b][s][h*64+d]
    split_wT_kernel<<<cw_grid, cw_blk>>>(Wk, whi, wlo);
    split_act_kernel<<<ca_grid, 256>>>((const float4*)key_,
                                       (__nv_bfloat162*)ahi, (__nv_bfloat162*)alo);
    gemm_tc_kernel<<<g_grid, 256, GT_SMEM_TOTAL>>>(ahi, alo, whi, wlo, bk, kh, 1, 1.0f);

    // Q projection -> fp16, pre-scaled by 1/8
    split_wT_kernel<<<cw_grid, cw_blk>>>(Wq, whi, wlo);
    split_act_kernel<<<ca_grid, 256>>>((const float4*)query,
                                       (__nv_bfloat162*)ahi, (__nv_bfloat162*)alo);
    gemm_tc_kernel<<<g_grid, 256, GT_SMEM_TOTAL>>>(ahi, alo, whi, wlo, bq, qh, 1, 0.125f);

    // attention (fp16 tensor cores)
    attn_tc_kernel<<<dim3(S_ / 128, B_ * H_), 256, AT_SMEM>>>(qh, kh, vt, go);

    // output projection (bf16-split, fp32 out)
    split_wT_kernel<<<cw_grid, cw_blk>>>(Wo, whi, wlo);
    split_act_kernel<<<ca_grid, 256>>>((const float4*)go,
                                       (__nv_bfloat162*)ahi, (__nv_bfloat162*)alo);
    gemm_tc_kernel<<<g_grid, 256, GT_SMEM_TOTAL>>>(ahi, alo, whi, wlo, bo, out, 0, 1.0f);
}